// round 11
// baseline (speedup 1.0000x reference)
#include <cuda_runtime.h>
#include <cuda_bf16.h>

#define NN 100000
#define EE 1600000
#define DD 64
#define SCAN_T 256
#define SCAN_NB 98                    // ceil(100000/1024), 4 items/thread

struct __align__(8) Edge { int c; float w; };

// ------------- device scratch (no allocations allowed) ---------------------
__device__ __align__(16) float g_y[NN * DD];   // y = x @ W^T
__device__ __align__(16) float g_deg[NN];
__device__ float g_dinv[NN];
__device__ __align__(16) int g_cnt[NN + 4];    // per-row edge count (pad for int4)
__device__ __align__(16) int g_pos[NN + 4];    // fill cursors (seeded to row starts)
__device__ int   g_off[NN + 1];                // CSR row offsets
__device__ unsigned g_state[SCAN_NB];          // lookback state: tag<<30 | value
__device__ Edge  g_e[EE];                      // CSR edges {col, w*dinv[col]}

// ---------------------------------------------------------------------------
// K0: reset counters / lookback flags, deg = 1.0 (self loop)
__global__ void k_init(int n) {
    int i = blockIdx.x * blockDim.x + threadIdx.x;
    if (i < n) {
        g_cnt[i] = 0;
        g_deg[i] = 1.0f;
    }
    if (i < SCAN_NB) g_state[i] = 0u;
    if (i == 0) g_off[0] = 0;
}

// K1: per-edge: count rows, accumulate degree. 4 edges/thread, vector loads.
__global__ void k_count(const int* __restrict__ rows,
                        const float* __restrict__ w, int e) {
    int q = blockIdx.x * blockDim.x + threadIdx.x;   // quad index
    int i0 = q * 4;
    if (i0 + 3 < e) {
        int4   r4 = ((const int4*)rows)[q];
        float4 w4 = ((const float4*)w)[q];
        atomicAdd(&g_cnt[r4.x], 1); atomicAdd(&g_deg[r4.x], w4.x);
        atomicAdd(&g_cnt[r4.y], 1); atomicAdd(&g_deg[r4.y], w4.y);
        atomicAdd(&g_cnt[r4.z], 1); atomicAdd(&g_deg[r4.z], w4.z);
        atomicAdd(&g_cnt[r4.w], 1); atomicAdd(&g_deg[r4.w], w4.w);
    } else {
        for (int i = i0; i < e; i++) {
            int r = rows[i];
            atomicAdd(&g_cnt[r], 1);
            atomicAdd(&g_deg[r], w[i]);
        }
    }
}

// K2: single-kernel exclusive scan of g_cnt via decoupled lookback.
// Also writes g_off[i+1], seeds g_pos[i] = row start, computes g_dinv.
// 98 blocks = one wave on 148 SMs; spin has nanosleep backoff.
__global__ __launch_bounds__(SCAN_T) void k_scan(int n) {
    __shared__ int wsum[8];
    __shared__ int s_bexcl;
    int tid  = threadIdx.x;
    int lane = tid & 31, wid = tid >> 5;
    int b    = blockIdx.x;
    int gid4 = b * SCAN_T + tid;                 // int4 index
    int i0   = gid4 * 4;

    int4 cv = (i0 + 3 < n) ? ((const int4*)g_cnt)[gid4] : make_int4(
        (i0 < n) ? g_cnt[i0] : 0,
        (i0 + 1 < n) ? g_cnt[i0 + 1] : 0,
        (i0 + 2 < n) ? g_cnt[i0 + 2] : 0,
        (i0 + 3 < n) ? g_cnt[i0 + 3] : 0);

    int s0 = cv.x, s1 = s0 + cv.y, s2 = s1 + cv.z, s3 = s2 + cv.w;

    // warp inclusive scan of per-thread sums
    int v = s3;
    #pragma unroll
    for (int off = 1; off < 32; off <<= 1) {
        int t = __shfl_up_sync(0xFFFFFFFFu, v, off);
        if (lane >= off) v += t;
    }
    if (lane == 31) wsum[wid] = v;
    __syncthreads();

    if (wid == 0 && lane < 8) {
        int t = wsum[lane];
        #pragma unroll
        for (int off = 1; off < 8; off <<= 1) {
            int u = __shfl_up_sync(0xFFu, t, off);
            if (lane >= off) t += u;
        }
        wsum[lane] = t;
    }
    __syncthreads();

    int block_total = wsum[7];
    int warp_excl   = (wid > 0) ? wsum[wid - 1] : 0;
    int thr_excl    = warp_excl + (v - s3);

    // decoupled lookback (thread 0), nanosleep backoff
    if (tid == 0) {
        if (b == 0) {
            atomicExch(&g_state[0], (2u << 30) | (unsigned)block_total);
            s_bexcl = 0;
        } else {
            atomicExch(&g_state[b], (1u << 30) | (unsigned)block_total);
            unsigned excl = 0;
            int p = b - 1;
            while (true) {
                unsigned st = atomicAdd(&g_state[p], 0u);
                unsigned tag = st >> 30;
                if (tag == 0u) { __nanosleep(40); continue; }
                excl += st & 0x3FFFFFFFu;
                if (tag == 2u) break;
                p--;
            }
            atomicExch(&g_state[b], (2u << 30) | (unsigned)(excl + block_total));
            s_bexcl = (int)excl;
        }
    }
    __syncthreads();

    int base = s_bexcl + thr_excl;
    if (i0 < n) {
        if (i0 + 3 < n) {
            ((int4*)g_pos)[gid4] = make_int4(base, base + s0, base + s1, base + s2);
            g_off[i0 + 1] = base + s0;
            g_off[i0 + 2] = base + s1;
            g_off[i0 + 3] = base + s2;
            g_off[i0 + 4] = base + s3;
            float4 dg = ((const float4*)g_deg)[gid4];
            g_dinv[i0]     = rsqrtf(dg.x);
            g_dinv[i0 + 1] = rsqrtf(dg.y);
            g_dinv[i0 + 2] = rsqrtf(dg.z);
            g_dinv[i0 + 3] = rsqrtf(dg.w);
        } else {
            int pref[4] = {base, base + s0, base + s1, base + s2};
            int incl[4] = {base + s0, base + s1, base + s2, base + s3};
            for (int k = 0; k < 4 && i0 + k < n; k++) {
                g_pos[i0 + k] = pref[k];
                g_off[i0 + k + 1] = incl[k];
                g_dinv[i0 + k] = rsqrtf(g_deg[i0 + k]);
            }
        }
    }
}

// K3: scatter edges into CSR slots. 4 edges/thread, vector loads.
__global__ void k_fill(const int* __restrict__ rows,
                       const int* __restrict__ cols,
                       const float* __restrict__ w, int e) {
    int q = blockIdx.x * blockDim.x + threadIdx.x;
    int i0 = q * 4;
    if (i0 + 3 < e) {
        int4   r4 = ((const int4*)rows)[q];
        int4   c4 = ((const int4*)cols)[q];
        float4 w4 = ((const float4*)w)[q];
        Edge ed;
        int slot;
        slot = atomicAdd(&g_pos[r4.x], 1);
        ed.c = c4.x; ed.w = w4.x * g_dinv[c4.x]; g_e[slot] = ed;
        slot = atomicAdd(&g_pos[r4.y], 1);
        ed.c = c4.y; ed.w = w4.y * g_dinv[c4.y]; g_e[slot] = ed;
        slot = atomicAdd(&g_pos[r4.z], 1);
        ed.c = c4.z; ed.w = w4.z * g_dinv[c4.z]; g_e[slot] = ed;
        slot = atomicAdd(&g_pos[r4.w], 1);
        ed.c = c4.w; ed.w = w4.w * g_dinv[c4.w]; g_e[slot] = ed;
    } else {
        for (int i = i0; i < e; i++) {
            int r = rows[i];
            int c = cols[i];
            int slot = atomicAdd(&g_pos[r], 1);
            Edge ed;
            ed.c = c;
            ed.w = w[i] * g_dinv[c];
            g_e[slot] = ed;
        }
    }
}

// K4: y = x @ W^T via packed fma.rn.f32x2 (full-rate fp32 on sm_103a)
__global__ __launch_bounds__(256) void k_gemm(const float* __restrict__ x,
                                              const float* __restrict__ W,
                                              int n) {
    __shared__ float sXt[64 * 66];
    __shared__ float sWt[64 * 66];
    int tid = threadIdx.x;
    int base = blockIdx.x * 64;

    #pragma unroll 4
    for (int idx = tid; idx < 64 * 64; idx += 256) {
        int r = idx >> 6, kk = idx & 63;
        sWt[kk * 66 + r] = W[idx];
        int gr = base + r;
        sXt[kk * 66 + r] = (gr < n) ? x[(size_t)gr * 64 + kk] : 0.0f;
    }
    __syncthreads();

    int og = tid >> 5;
    int ng = tid & 31;

    unsigned long long accA[4], accB[4];
    #pragma unroll
    for (int j = 0; j < 4; j++) { accA[j] = 0ull; accB[j] = 0ull; }

    const float2* X2 = (const float2*)sXt;
    const unsigned long long* W2 = (const unsigned long long*)sWt;

    #pragma unroll 4
    for (int k = 0; k < 64; k++) {
        float2 a = X2[k * 33 + ng];
        unsigned long long ax, ay;
        asm("mov.b64 %0, {%1,%1};" : "=l"(ax) : "f"(a.x));
        asm("mov.b64 %0, {%1,%1};" : "=l"(ay) : "f"(a.y));
        #pragma unroll
        for (int j = 0; j < 4; j++) {
            unsigned long long wp = W2[k * 33 + og * 4 + j];
            asm("fma.rn.f32x2 %0, %1, %2, %0;" : "+l"(accA[j]) : "l"(ax), "l"(wp));
            asm("fma.rn.f32x2 %0, %1, %2, %0;" : "+l"(accB[j]) : "l"(ay), "l"(wp));
        }
    }

    int node0 = base + 2 * ng;
    float o[8];
    if (node0 < n) {
        #pragma unroll
        for (int j = 0; j < 4; j++)
            asm("mov.b64 {%0,%1}, %2;" : "=f"(o[2*j]), "=f"(o[2*j+1]) : "l"(accA[j]));
        float4* p = (float4*)(g_y + (size_t)node0 * 64 + og * 8);
        p[0] = make_float4(o[0], o[1], o[2], o[3]);
        p[1] = make_float4(o[4], o[5], o[6], o[7]);
    }
    if (node0 + 1 < n) {
        #pragma unroll
        for (int j = 0; j < 4; j++)
            asm("mov.b64 {%0,%1}, %2;" : "=f"(o[2*j]), "=f"(o[2*j+1]) : "l"(accB[j]));
        float4* p = (float4*)(g_y + (size_t)(node0 + 1) * 64 + og * 8);
        p[0] = make_float4(o[0], o[1], o[2], o[3]);
        p[1] = make_float4(o[4], o[5], o[6], o[7]);
    }
}

// K5: gather-SpMM. 16 lanes per row, one float4 per lane. No atomics.
__global__ __launch_bounds__(256) void k_gather(const float* __restrict__ b,
                                                float* __restrict__ out, int n) {
    int tid = threadIdx.x;
    int grp = tid >> 4;
    int c   = tid & 15;
    int r   = blockIdx.x * 16 + grp;
    if (r >= n) return;

    const float4* Y = (const float4*)g_y;
    int beg = g_off[r];
    int end = g_off[r + 1];

    float4 acc = make_float4(0.f, 0.f, 0.f, 0.f);
    int j = beg;
    for (; j + 3 < end; j += 4) {
        Edge e0 = g_e[j],     e1 = g_e[j + 1];
        Edge e2 = g_e[j + 2], e3 = g_e[j + 3];
        float4 y0 = Y[(size_t)e0.c * 16 + c];
        float4 y1 = Y[(size_t)e1.c * 16 + c];
        float4 y2 = Y[(size_t)e2.c * 16 + c];
        float4 y3 = Y[(size_t)e3.c * 16 + c];
        acc.x = fmaf(e0.w, y0.x, acc.x); acc.y = fmaf(e0.w, y0.y, acc.y);
        acc.z = fmaf(e0.w, y0.z, acc.z); acc.w = fmaf(e0.w, y0.w, acc.w);
        acc.x = fmaf(e1.w, y1.x, acc.x); acc.y = fmaf(e1.w, y1.y, acc.y);
        acc.z = fmaf(e1.w, y1.z, acc.z); acc.w = fmaf(e1.w, y1.w, acc.w);
        acc.x = fmaf(e2.w, y2.x, acc.x); acc.y = fmaf(e2.w, y2.y, acc.y);
        acc.z = fmaf(e2.w, y2.z, acc.z); acc.w = fmaf(e2.w, y2.w, acc.w);
        acc.x = fmaf(e3.w, y3.x, acc.x); acc.y = fmaf(e3.w, y3.y, acc.y);
        acc.z = fmaf(e3.w, y3.z, acc.z); acc.w = fmaf(e3.w, y3.w, acc.w);
    }
    for (; j < end; j++) {
        Edge e0 = g_e[j];
        float4 y0 = Y[(size_t)e0.c * 16 + c];
        acc.x = fmaf(e0.w, y0.x, acc.x); acc.y = fmaf(e0.w, y0.y, acc.y);
        acc.z = fmaf(e0.w, y0.z, acc.z); acc.w = fmaf(e0.w, y0.w, acc.w);
    }

    float dv = g_dinv[r];
    float s = dv * dv;
    float4 yr = Y[(size_t)r * 16 + c];
    float4 bv = ((const float4*)b)[c];
    float4 o;
    o.x = fmaf(dv, acc.x, fmaf(s, yr.x, bv.x));
    o.y = fmaf(dv, acc.y, fmaf(s, yr.y, bv.y));
    o.z = fmaf(dv, acc.z, fmaf(s, yr.z, bv.z));
    o.w = fmaf(dv, acc.w, fmaf(s, yr.w, bv.w));
    ((float4*)out)[(size_t)r * 16 + c] = o;
}

// ---------------------------------------------------------------------------
extern "C" void kernel_launch(void* const* d_in, const int* in_sizes, int n_in,
                              void* d_out, int out_size) {
    const float* x  = (const float*)d_in[0];
    const int*   ei = (const int*)d_in[1];     // INT32 [2, E]
    const float* w  = (const float*)d_in[2];
    const float* W  = (const float*)d_in[3];
    const float* b  = (const float*)d_in[4];
    float* out = (float*)d_out;

    int n = in_sizes[0] / DD;       // 100000
    int e = in_sizes[2];            // 1600000
    const int* rows = ei;
    const int* cols = ei + e;

    static cudaStream_t s2 = nullptr;
    static cudaEvent_t evFork = nullptr, evGemm = nullptr;
    if (!s2) {
        cudaStreamCreateWithFlags(&s2, cudaStreamNonBlocking);
        cudaEventCreateWithFlags(&evFork, cudaEventDisableTiming);
        cudaEventCreateWithFlags(&evGemm, cudaEventDisableTiming);
    }

    const int T = 256;
    int eq = (e + 3) / 4;           // quads for count/fill

    // fork: GEMM runs concurrently with the CSR build
    cudaEventRecord(evFork, 0);
    cudaStreamWaitEvent(s2, evFork, 0);
    k_gemm<<<(n + 63) / 64, T, 0, s2>>>(x, W, n);
    cudaEventRecord(evGemm, s2);

    // main chain: CSR build
    k_init <<<(n + T - 1) / T, T>>>(n);
    k_count<<<(eq + T - 1) / T, T>>>(rows, w, e);
    k_scan <<<SCAN_NB, SCAN_T>>>(n);
    k_fill <<<(eq + T - 1) / T, T>>>(rows, cols, w, e);

    // join, then gather
    cudaStreamWaitEvent(0, evGemm, 0);
    k_gather<<<(n + 15) / 16, T>>>(b, out, n);
}

// round 13
// speedup vs baseline: 1.1409x; 1.1409x over previous
#include <cuda_runtime.h>
#include <cuda_fp16.h>

#define NN 100000
#define EE 1600000
#define DD 64
#define SCAN_T 256
#define SCAN_NB 98                    // ceil(100000/1024), 4 items/thread

struct __align__(8) Edge { int c; float w; };

// ------------- device scratch (no allocations allowed) ---------------------
__device__ __align__(16) __half g_yh[NN * DD]; // y = x @ W^T (fp16 storage)
__device__ __align__(16) float g_deg[NN];
__device__ float g_dinv[NN];
__device__ __align__(16) int g_cnt[NN + 4];
__device__ __align__(16) int g_pos[NN + 4];    // fill cursors (seeded to row starts)
__device__ int   g_off[NN + 1];
__device__ unsigned g_state[SCAN_NB];          // lookback: tag<<30 | value
__device__ Edge  g_e[EE];                      // CSR edges {col, w*dinv[col]}

// ---------------------------------------------------------------------------
__global__ void k_init(int n) {
    int i = blockIdx.x * blockDim.x + threadIdx.x;
    if (i < n) {
        g_cnt[i] = 0;
        g_deg[i] = 1.0f;
    }
    if (i < SCAN_NB) g_state[i] = 0u;
    if (i == 0) g_off[0] = 0;
}

// K1: count rows + accumulate degree. 4 edges/thread, vector loads.
__global__ void k_count(const int* __restrict__ rows,
                        const float* __restrict__ w, int e) {
    int q = blockIdx.x * blockDim.x + threadIdx.x;
    int i0 = q * 4;
    if (i0 + 3 < e) {
        int4   r4 = ((const int4*)rows)[q];
        float4 w4 = ((const float4*)w)[q];
        atomicAdd(&g_cnt[r4.x], 1); atomicAdd(&g_deg[r4.x], w4.x);
        atomicAdd(&g_cnt[r4.y], 1); atomicAdd(&g_deg[r4.y], w4.y);
        atomicAdd(&g_cnt[r4.z], 1); atomicAdd(&g_deg[r4.z], w4.z);
        atomicAdd(&g_cnt[r4.w], 1); atomicAdd(&g_deg[r4.w], w4.w);
    } else {
        for (int i = i0; i < e; i++) {
            int r = rows[i];
            atomicAdd(&g_cnt[r], 1);
            atomicAdd(&g_deg[r], w[i]);
        }
    }
}

// K2: fused exclusive scan, decoupled lookback with WARP-PARALLEL window.
__global__ __launch_bounds__(SCAN_T) void k_scan(int n) {
    __shared__ int wsum[8];
    __shared__ int s_bexcl;
    int tid  = threadIdx.x;
    int lane = tid & 31, wid = tid >> 5;
    int b    = blockIdx.x;
    int gid4 = b * SCAN_T + tid;
    int i0   = gid4 * 4;

    int4 cv = (i0 + 3 < n) ? ((const int4*)g_cnt)[gid4] : make_int4(
        (i0 < n) ? g_cnt[i0] : 0,
        (i0 + 1 < n) ? g_cnt[i0 + 1] : 0,
        (i0 + 2 < n) ? g_cnt[i0 + 2] : 0,
        (i0 + 3 < n) ? g_cnt[i0 + 3] : 0);

    int s0 = cv.x, s1 = s0 + cv.y, s2 = s1 + cv.z, s3 = s2 + cv.w;

    int v = s3;
    #pragma unroll
    for (int off = 1; off < 32; off <<= 1) {
        int t = __shfl_up_sync(0xFFFFFFFFu, v, off);
        if (lane >= off) v += t;
    }
    if (lane == 31) wsum[wid] = v;
    __syncthreads();

    if (wid == 0 && lane < 8) {
        int t = wsum[lane];
        #pragma unroll
        for (int off = 1; off < 8; off <<= 1) {
            int u = __shfl_up_sync(0xFFu, t, off);
            if (lane >= off) t += u;
        }
        wsum[lane] = t;
    }
    __syncthreads();

    int block_total = wsum[7];
    int warp_excl   = (wid > 0) ? wsum[wid - 1] : 0;
    int thr_excl    = warp_excl + (v - s3);

    // warp 0: parallel lookback, 32 predecessors per round
    if (wid == 0) {
        if (b == 0) {
            if (lane == 0) {
                atomicExch(&g_state[0], (2u << 30) | (unsigned)block_total);
                s_bexcl = 0;
            }
        } else {
            if (lane == 0)
                atomicExch(&g_state[b], (1u << 30) | (unsigned)block_total);
            __syncwarp();
            unsigned excl = 0;
            int p = b - 1;
            while (true) {
                int idx = p - lane;                       // lane0 = nearest pred
                unsigned st = (idx >= 0) ? atomicAdd(&g_state[idx], 0u)
                                         : (2u << 30);    // synthetic prefix 0
                unsigned tag = st >> 30;
                if (__ballot_sync(0xFFFFFFFFu, tag == 0u)) {
                    __nanosleep(20);
                    continue;                             // someone not ready
                }
                unsigned b2 = __ballot_sync(0xFFFFFFFFu, tag == 2u);
                unsigned val = st & 0x3FFFFFFFu;
                unsigned c;
                if (b2) {
                    int l2 = __ffs(b2) - 1;               // nearest full prefix
                    c = (lane <= (unsigned)l2) ? val : 0; // beyond l2 already counted
                } else {
                    c = val;                              // all partial: take all
                }
                #pragma unroll
                for (int o = 16; o; o >>= 1)
                    c += __shfl_xor_sync(0xFFFFFFFFu, c, o);
                excl += c;
                if (b2) break;
                p -= 32;
            }
            if (lane == 0) {
                atomicExch(&g_state[b], (2u << 30) | (unsigned)(excl + (unsigned)block_total));
                s_bexcl = (int)excl;
            }
        }
    }
    __syncthreads();

    int base = s_bexcl + thr_excl;
    if (i0 < n) {
        if (i0 + 3 < n) {
            ((int4*)g_pos)[gid4] = make_int4(base, base + s0, base + s1, base + s2);
            g_off[i0 + 1] = base + s0;
            g_off[i0 + 2] = base + s1;
            g_off[i0 + 3] = base + s2;
            g_off[i0 + 4] = base + s3;
            float4 dg = ((const float4*)g_deg)[gid4];
            g_dinv[i0]     = rsqrtf(dg.x);
            g_dinv[i0 + 1] = rsqrtf(dg.y);
            g_dinv[i0 + 2] = rsqrtf(dg.z);
            g_dinv[i0 + 3] = rsqrtf(dg.w);
        } else {
            int pref[4] = {base, base + s0, base + s1, base + s2};
            int incl[4] = {base + s0, base + s1, base + s2, base + s3};
            for (int k = 0; k < 4 && i0 + k < n; k++) {
                g_pos[i0 + k] = pref[k];
                g_off[i0 + k + 1] = incl[k];
                g_dinv[i0 + k] = rsqrtf(g_deg[i0 + k]);
            }
        }
    }
}

// K3: scatter edges into CSR slots. 4 edges/thread, vector loads.
__global__ void k_fill(const int* __restrict__ rows,
                       const int* __restrict__ cols,
                       const float* __restrict__ w, int e) {
    int q = blockIdx.x * blockDim.x + threadIdx.x;
    int i0 = q * 4;
    if (i0 + 3 < e) {
        int4   r4 = ((const int4*)rows)[q];
        int4   c4 = ((const int4*)cols)[q];
        float4 w4 = ((const float4*)w)[q];
        Edge ed;
        int slot;
        slot = atomicAdd(&g_pos[r4.x], 1);
        ed.c = c4.x; ed.w = w4.x * g_dinv[c4.x]; g_e[slot] = ed;
        slot = atomicAdd(&g_pos[r4.y], 1);
        ed.c = c4.y; ed.w = w4.y * g_dinv[c4.y]; g_e[slot] = ed;
        slot = atomicAdd(&g_pos[r4.z], 1);
        ed.c = c4.z; ed.w = w4.z * g_dinv[c4.z]; g_e[slot] = ed;
        slot = atomicAdd(&g_pos[r4.w], 1);
        ed.c = c4.w; ed.w = w4.w * g_dinv[c4.w]; g_e[slot] = ed;
    } else {
        for (int i = i0; i < e; i++) {
            int r = rows[i];
            int c = cols[i];
            int slot = atomicAdd(&g_pos[r], 1);
            Edge ed;
            ed.c = c;
            ed.w = w[i] * g_dinv[c];
            g_e[slot] = ed;
        }
    }
}

// K4: y = x @ W^T via packed fma.rn.f32x2; fp32 accumulate, fp16 store.
__global__ __launch_bounds__(256) void k_gemm(const float* __restrict__ x,
                                              const float* __restrict__ W,
                                              int n) {
    __shared__ float sXt[64 * 66];
    __shared__ float sWt[64 * 66];
    int tid = threadIdx.x;
    int base = blockIdx.x * 64;

    #pragma unroll 4
    for (int idx = tid; idx < 64 * 64; idx += 256) {
        int r = idx >> 6, kk = idx & 63;
        sWt[kk * 66 + r] = W[idx];
        int gr = base + r;
        sXt[kk * 66 + r] = (gr < n) ? x[(size_t)gr * 64 + kk] : 0.0f;
    }
    __syncthreads();

    int og = tid >> 5;
    int ng = tid & 31;

    unsigned long long accA[4], accB[4];
    #pragma unroll
    for (int j = 0; j < 4; j++) { accA[j] = 0ull; accB[j] = 0ull; }

    const float2* X2 = (const float2*)sXt;
    const unsigned long long* W2 = (const unsigned long long*)sWt;

    #pragma unroll 4
    for (int k = 0; k < 64; k++) {
        float2 a = X2[k * 33 + ng];
        unsigned long long ax, ay;
        asm("mov.b64 %0, {%1,%1};" : "=l"(ax) : "f"(a.x));
        asm("mov.b64 %0, {%1,%1};" : "=l"(ay) : "f"(a.y));
        #pragma unroll
        for (int j = 0; j < 4; j++) {
            unsigned long long wp = W2[k * 33 + og * 4 + j];
            asm("fma.rn.f32x2 %0, %1, %2, %0;" : "+l"(accA[j]) : "l"(ax), "l"(wp));
            asm("fma.rn.f32x2 %0, %1, %2, %0;" : "+l"(accB[j]) : "l"(ay), "l"(wp));
        }
    }

    int node0 = base + 2 * ng;
    float o[8];
    union { __half2 h[4]; uint4 u; } pk;
    if (node0 < n) {
        #pragma unroll
        for (int j = 0; j < 4; j++)
            asm("mov.b64 {%0,%1}, %2;" : "=f"(o[2*j]), "=f"(o[2*j+1]) : "l"(accA[j]));
        #pragma unroll
        for (int j = 0; j < 4; j++) pk.h[j] = __floats2half2_rn(o[2*j], o[2*j+1]);
        *(uint4*)(g_yh + (size_t)node0 * 64 + og * 8) = pk.u;
    }
    if (node0 + 1 < n) {
        #pragma unroll
        for (int j = 0; j < 4; j++)
            asm("mov.b64 {%0,%1}, %2;" : "=f"(o[2*j]), "=f"(o[2*j+1]) : "l"(accB[j]));
        #pragma unroll
        for (int j = 0; j < 4; j++) pk.h[j] = __floats2half2_rn(o[2*j], o[2*j+1]);
        *(uint4*)(g_yh + (size_t)(node0 + 1) * 64 + og * 8) = pk.u;
    }
}

// K5: gather-SpMM. 16 lanes per row, 4 halfs (8 B) per lane. fp32 accumulate.
__global__ __launch_bounds__(256) void k_gather(const float* __restrict__ b,
                                                float* __restrict__ out, int n) {
    int tid = threadIdx.x;
    int grp = tid >> 4;
    int c   = tid & 15;              // 4-half chunk within row
    int r   = blockIdx.x * 16 + grp;
    if (r >= n) return;

    const __half2* Y = (const __half2*)g_yh;   // row = 32 half2
    int beg = g_off[r];
    int end = g_off[r + 1];

    float4 acc = make_float4(0.f, 0.f, 0.f, 0.f);
    int j = beg;
    for (; j + 3 < end; j += 4) {
        Edge e0 = g_e[j],     e1 = g_e[j + 1];
        Edge e2 = g_e[j + 2], e3 = g_e[j + 3];
        #pragma unroll
        for (int t = 0; t < 4; t++) {
            Edge ee = (t == 0) ? e0 : (t == 1) ? e1 : (t == 2) ? e2 : e3;
            size_t p = (size_t)ee.c * 32 + c * 2;
            float2 f0 = __half22float2(Y[p]);
            float2 f1 = __half22float2(Y[p + 1]);
            acc.x = fmaf(ee.w, f0.x, acc.x); acc.y = fmaf(ee.w, f0.y, acc.y);
            acc.z = fmaf(ee.w, f1.x, acc.z); acc.w = fmaf(ee.w, f1.y, acc.w);
        }
    }
    for (; j < end; j++) {
        Edge ee = g_e[j];
        size_t p = (size_t)ee.c * 32 + c * 2;
        float2 f0 = __half22float2(Y[p]);
        float2 f1 = __half22float2(Y[p + 1]);
        acc.x = fmaf(ee.w, f0.x, acc.x); acc.y = fmaf(ee.w, f0.y, acc.y);
        acc.z = fmaf(ee.w, f1.x, acc.z); acc.w = fmaf(ee.w, f1.y, acc.w);
    }

    float dv = g_dinv[r];
    float s = dv * dv;
    size_t pr = (size_t)r * 32 + c * 2;
    float2 y0 = __half22float2(Y[pr]);
    float2 y1 = __half22float2(Y[pr + 1]);
    float4 bv = ((const float4*)b)[c];
    float4 o;
    o.x = fmaf(dv, acc.x, fmaf(s, y0.x, bv.x));
    o.y = fmaf(dv, acc.y, fmaf(s, y0.y, bv.y));
    o.z = fmaf(dv, acc.z, fmaf(s, y1.x, bv.z));
    o.w = fmaf(dv, acc.w, fmaf(s, y1.y, bv.w));
    ((float4*)out)[(size_t)r * 16 + c] = o;
}

// ---------------------------------------------------------------------------
extern "C" void kernel_launch(void* const* d_in, const int* in_sizes, int n_in,
                              void* d_out, int out_size) {
    const float* x  = (const float*)d_in[0];
    const int*   ei = (const int*)d_in[1];     // INT32 [2, E]
    const float* w  = (const float*)d_in[2];
    const float* W  = (const float*)d_in[3];
    const float* b  = (const float*)d_in[4];
    float* out = (float*)d_out;

    int n = in_sizes[0] / DD;       // 100000
    int e = in_sizes[2];            // 1600000
    const int* rows = ei;
    const int* cols = ei + e;

    static cudaStream_t s2 = nullptr;
    static cudaEvent_t evFork = nullptr, evGemm = nullptr;
    if (!s2) {
        cudaStreamCreateWithFlags(&s2, cudaStreamNonBlocking);
        cudaEventCreateWithFlags(&evFork, cudaEventDisableTiming);
        cudaEventCreateWithFlags(&evGemm, cudaEventDisableTiming);
    }

    const int T = 256;
    int eq = (e + 3) / 4;

    // fork: GEMM runs concurrently with the CSR build
    cudaEventRecord(evFork, 0);
    cudaStreamWaitEvent(s2, evFork, 0);
    k_gemm<<<(n + 63) / 64, T, 0, s2>>>(x, W, n);
    cudaEventRecord(evGemm, s2);

    // main chain: CSR build
    k_init <<<(n + T - 1) / T, T>>>(n);
    k_count<<<(eq + T - 1) / T, T>>>(rows, w, e);
    k_scan <<<SCAN_NB, SCAN_T>>>(n);
    k_fill <<<(eq + T - 1) / T, T>>>(rows, cols, w, e);

    // join, then gather
    cudaStreamWaitEvent(0, evGemm, 0);
    k_gather<<<(n + 15) / 16, T>>>(b, out, n);
}